// round 2
// baseline (speedup 1.0000x reference)
#include <cuda_runtime.h>

#define NE 2000
#define NB 8
#define NHID 256
#define ALPHA 0.2f
#define MASKF 9e-15f
#define L2E 1.4426950408889634f

// Device scratch (no allocations allowed)
__device__ float g_s2[NE];
__device__ float g_h0[NE];
__device__ float g_h1[NE];
__device__ float g_h2[NE];
__device__ float g_s1[NE];
__device__ float g_x[NB * NE * 3];   // elu(h_prime) flattened [b][i*3+d]

__device__ __forceinline__ float ex2f(float x) {
    float y;
    asm("ex2.approx.ftz.f32 %0, %1;" : "=f"(y) : "f"(x));
    return y;
}

// ---------------- Kernel A: h = emb @ W ; s1 = h@a[:3] ; s2 = h@a[3:] ----------------
__global__ void kA(const float* __restrict__ emb,
                   const float* __restrict__ W,
                   const float* __restrict__ a) {
    __shared__ float Ws[64 * 3];
    __shared__ float as[6];
    int tid = threadIdx.x;
    if (tid < 192) Ws[tid] = W[tid];
    if (tid < 6)   as[tid] = a[tid];
    __syncthreads();

    int j = blockIdx.x * blockDim.x + tid;
    if (j >= NE) return;

    const float4* er = reinterpret_cast<const float4*>(emb + (size_t)j * 64);
    float h0 = 0.f, h1 = 0.f, h2 = 0.f;
#pragma unroll
    for (int q = 0; q < 16; q++) {
        float4 v = er[q];
        int k = q * 4;
        h0 = fmaf(v.x, Ws[(k + 0) * 3 + 0], h0);
        h1 = fmaf(v.x, Ws[(k + 0) * 3 + 1], h1);
        h2 = fmaf(v.x, Ws[(k + 0) * 3 + 2], h2);
        h0 = fmaf(v.y, Ws[(k + 1) * 3 + 0], h0);
        h1 = fmaf(v.y, Ws[(k + 1) * 3 + 1], h1);
        h2 = fmaf(v.y, Ws[(k + 1) * 3 + 2], h2);
        h0 = fmaf(v.z, Ws[(k + 2) * 3 + 0], h0);
        h1 = fmaf(v.z, Ws[(k + 2) * 3 + 1], h1);
        h2 = fmaf(v.z, Ws[(k + 2) * 3 + 2], h2);
        h0 = fmaf(v.w, Ws[(k + 3) * 3 + 0], h0);
        h1 = fmaf(v.w, Ws[(k + 3) * 3 + 1], h1);
        h2 = fmaf(v.w, Ws[(k + 3) * 3 + 2], h2);
    }
    g_h0[j] = h0; g_h1[j] = h1; g_h2[j] = h2;
    g_s1[j] = h0 * as[0] + h1 * as[1] + h2 * as[2];
    g_s2[j] = h0 * as[3] + h1 * as[4] + h2 * as[5];
}

// ---------------- Kernel B: masked softmax + aggregation + ELU ----------------
// One warp per i (all 8 batches). 250 CTAs x 8 warps = 2000 warps.
__global__ __launch_bounds__(256) void kB(const int* __restrict__ adj) {
    __shared__ float ss2[NE];
    __shared__ float sh0[NE];
    __shared__ float sh1[NE];
    __shared__ float sh2[NE];
    __shared__ float redbuf[8];

    int tid = threadIdx.x;
    int lane = tid & 31;
    int wid = tid >> 5;

    float mx = -1e30f;
    for (int j = tid; j < NE; j += 256) {
        float v2 = g_s2[j];
        ss2[j] = v2;
        sh0[j] = g_h0[j];
        sh1[j] = g_h1[j];
        sh2[j] = g_h2[j];
        mx = fmaxf(mx, v2);
    }
#pragma unroll
    for (int o = 16; o; o >>= 1) mx = fmaxf(mx, __shfl_xor_sync(~0u, mx, o));
    if (lane == 0) redbuf[wid] = mx;
    __syncthreads();
    float s2max = redbuf[0];
#pragma unroll
    for (int w = 1; w < 8; w++) s2max = fmaxf(s2max, redbuf[w]);

    int i = blockIdx.x * 8 + wid;     // 0..1999
    float s1i = g_s1[i];
    float ts = s1i + s2max;
    float c = fmaxf(fmaxf(ts, ALPHA * ts), MASKF);   // valid softmax shift
    float negc = -c * L2E;
    float w0 = ex2f(fmaf(MASKF, L2E, negc));         // weight of masked entries

    const int* base = adj + (size_t)i * NE;          // + b*NE*NE per batch

    float Zb[8], A0[8], A1[8], A2[8];
#pragma unroll
    for (int b = 0; b < 8; b++) { Zb[b] = 0.f; A0[b] = 0.f; A1[b] = 0.f; A2[b] = 0.f; }

#define PROC_K(COMP) do {                                                    \
        float t  = s1i + s2v.COMP;                                           \
        float e  = fmaxf(t, ALPHA * t);                                      \
        float wf = ex2f(fmaf(e, L2E, negc));                                 \
        float hj0 = h0v.COMP, hj1 = h1v.COMP, hj2 = h2v.COMP;                \
        _Pragma("unroll")                                                    \
        for (int b = 0; b < 8; b++) {                                        \
            float w = (av[b].COMP != 0) ? wf : w0;                           \
            Zb[b] += w;                                                      \
            A0[b] = fmaf(w, hj0, A0[b]);                                     \
            A1[b] = fmaf(w, hj1, A1[b]);                                     \
            A2[b] = fmaf(w, hj2, A2[b]);                                     \
        }                                                                    \
    } while (0)

#pragma unroll 2
    for (int it = 0; it < 16; it++) {
        int j0 = it * 128 + lane * 4;
        if (j0 < NE) {
            int4 av[8];
#pragma unroll
            for (int b = 0; b < 8; b++)
                av[b] = *reinterpret_cast<const int4*>(base + (size_t)b * NE * NE + j0);
            float4 s2v = *reinterpret_cast<const float4*>(&ss2[j0]);
            float4 h0v = *reinterpret_cast<const float4*>(&sh0[j0]);
            float4 h1v = *reinterpret_cast<const float4*>(&sh1[j0]);
            float4 h2v = *reinterpret_cast<const float4*>(&sh2[j0]);
            PROC_K(x);
            PROC_K(y);
            PROC_K(z);
            PROC_K(w);
        }
    }
#undef PROC_K

    // warp reductions (32 accumulators)
#pragma unroll
    for (int b = 0; b < 8; b++) {
#pragma unroll
        for (int o = 16; o; o >>= 1) {
            Zb[b] += __shfl_xor_sync(~0u, Zb[b], o);
            A0[b] += __shfl_xor_sync(~0u, A0[b], o);
            A1[b] += __shfl_xor_sync(~0u, A1[b], o);
            A2[b] += __shfl_xor_sync(~0u, A2[b], o);
        }
    }

    if (lane == 0) {
#pragma unroll
        for (int b = 0; b < 8; b++) {
            float inv = 1.0f / Zb[b];
            float p0 = A0[b] * inv;
            float p1 = A1[b] * inv;
            float p2 = A2[b] * inv;
            float x0 = (p0 > 0.f) ? p0 : expm1f(p0);
            float x1 = (p1 > 0.f) ? p1 : expm1f(p1);
            float x2 = (p2 > 0.f) ? p2 : expm1f(p2);
            float* xp = g_x + (size_t)b * (NE * 3) + (size_t)i * 3;
            xp[0] = x0; xp[1] = x1; xp[2] = x2;
        }
    }
}

// ---------------- Kernel C: out[b,k] = x[b,:] . fc1_w[k,:] + fc1_b[k] ----------------
__global__ __launch_bounds__(256) void kC(const float* __restrict__ fw,
                                          const float* __restrict__ fb,
                                          float* __restrict__ out) {
    int k = blockIdx.x;
    int tid = threadIdx.x;
    int lane = tid & 31;
    int wid = tid >> 5;
    const float* wr = fw + (size_t)k * (NE * 3);

    float acc[8];
#pragma unroll
    for (int b = 0; b < 8; b++) acc[b] = 0.f;

    for (int m = tid; m < NE * 3; m += 256) {
        float wv = wr[m];
#pragma unroll
        for (int b = 0; b < 8; b++)
            acc[b] = fmaf(wv, g_x[(size_t)b * (NE * 3) + m], acc[b]);
    }

#pragma unroll
    for (int b = 0; b < 8; b++)
#pragma unroll
        for (int o = 16; o; o >>= 1)
            acc[b] += __shfl_xor_sync(~0u, acc[b], o);

    __shared__ float sred[8][8];
    if (lane == 0) {
#pragma unroll
        for (int b = 0; b < 8; b++) sred[wid][b] = acc[b];
    }
    __syncthreads();
    if (tid < 8) {
        float s = fb[k];
#pragma unroll
        for (int w = 0; w < 8; w++) s += sred[w][tid];
        out[(size_t)tid * NHID + k] = s;
    }
}

extern "C" void kernel_launch(void* const* d_in, const int* in_sizes, int n_in,
                              void* d_out, int out_size) {
    const float* emb   = (const float*)d_in[0];
    const float* W     = (const float*)d_in[1];
    const float* a     = (const float*)d_in[2];
    const float* fc1_w = (const float*)d_in[3];
    const float* fc1_b = (const float*)d_in[4];
    const int*   adj   = (const int*)d_in[5];
    float* out = (float*)d_out;

    kA<<<8, 256>>>(emb, W, a);
    kB<<<250, 256>>>(adj);
    kC<<<NHID, 256>>>(fc1_w, fc1_b, out);
}

// round 3
// speedup vs baseline: 1.0084x; 1.0084x over previous
#include <cuda_runtime.h>

#define NE 2000
#define NB 8
#define NHID 256
#define ALPHA 0.2f
#define MASKF 9e-15f
#define L2E 1.4426950408889634f

// Device scratch (no allocations allowed)
__device__ float g_s2[NE];
__device__ float g_h0[NE];
__device__ float g_h1[NE];
__device__ float g_h2[NE];
__device__ float g_s1[NE];
__device__ float g_x[NB * NE * 3];   // elu(h_prime) flattened [b][i*3+d]

__device__ __forceinline__ float ex2f(float x) {
    float y;
    asm("ex2.approx.ftz.f32 %0, %1;" : "=f"(y) : "f"(x));
    return y;
}

// ---------------- Kernel A: h = emb @ W ; s1 = h@a[:3] ; s2 = h@a[3:] ----------------
// One warp per row j. 250 CTAs x 8 warps = 2000 warps -> spread over all SMs.
__global__ __launch_bounds__(256) void kA(const float* __restrict__ emb,
                                          const float* __restrict__ W,
                                          const float* __restrict__ a) {
    __shared__ float Ws[64 * 3];
    __shared__ float as[6];
    int tid = threadIdx.x;
    if (tid < 192) Ws[tid] = W[tid];
    if (tid < 6)   as[tid] = a[tid];
    __syncthreads();

    int wid = tid >> 5;
    int lane = tid & 31;
    int j = blockIdx.x * 8 + wid;          // 0..1999 exactly

    float e0 = emb[(size_t)j * 64 + lane];
    float e1 = emb[(size_t)j * 64 + 32 + lane];

    float h0 = e0 * Ws[lane * 3 + 0] + e1 * Ws[(lane + 32) * 3 + 0];
    float h1 = e0 * Ws[lane * 3 + 1] + e1 * Ws[(lane + 32) * 3 + 1];
    float h2 = e0 * Ws[lane * 3 + 2] + e1 * Ws[(lane + 32) * 3 + 2];

#pragma unroll
    for (int o = 16; o; o >>= 1) {
        h0 += __shfl_xor_sync(~0u, h0, o);
        h1 += __shfl_xor_sync(~0u, h1, o);
        h2 += __shfl_xor_sync(~0u, h2, o);
    }

    if (lane == 0) {
        g_h0[j] = h0; g_h1[j] = h1; g_h2[j] = h2;
        g_s1[j] = h0 * as[0] + h1 * as[1] + h2 * as[2];
        g_s2[j] = h0 * as[3] + h1 * as[4] + h2 * as[5];
    }
}

// ---------------- Kernel B: masked softmax + aggregation + ELU ----------------
// One warp per i (all 8 batches). 250 CTAs x 8 warps = 2000 warps.
__global__ __launch_bounds__(256) void kB(const int* __restrict__ adj) {
    __shared__ float ss2[NE];
    __shared__ float sh0[NE];
    __shared__ float sh1[NE];
    __shared__ float sh2[NE];
    __shared__ float redbuf[8];

    int tid = threadIdx.x;
    int lane = tid & 31;
    int wid = tid >> 5;

    // Stage tables (float4) + block max of s2
    float mx = -1e30f;
    {
        const float4* p2 = reinterpret_cast<const float4*>(g_s2);
        const float4* p0 = reinterpret_cast<const float4*>(g_h0);
        const float4* p1 = reinterpret_cast<const float4*>(g_h1);
        const float4* p3 = reinterpret_cast<const float4*>(g_h2);
        float4* q2 = reinterpret_cast<float4*>(ss2);
        float4* q0 = reinterpret_cast<float4*>(sh0);
        float4* q1 = reinterpret_cast<float4*>(sh1);
        float4* q3 = reinterpret_cast<float4*>(sh2);
        for (int q = tid; q < NE / 4; q += 256) {
            float4 v2 = p2[q];
            q2[q] = v2;
            q0[q] = p0[q];
            q1[q] = p1[q];
            q3[q] = p3[q];
            mx = fmaxf(fmaxf(fmaxf(mx, v2.x), fmaxf(v2.y, v2.z)), v2.w);
        }
    }
#pragma unroll
    for (int o = 16; o; o >>= 1) mx = fmaxf(mx, __shfl_xor_sync(~0u, mx, o));
    if (lane == 0) redbuf[wid] = mx;
    __syncthreads();
    float s2max = redbuf[0];
#pragma unroll
    for (int w = 1; w < 8; w++) s2max = fmaxf(s2max, redbuf[w]);

    int i = blockIdx.x * 8 + wid;     // 0..1999
    float s1i = g_s1[i];
    float ts = s1i + s2max;
    float c = fmaxf(fmaxf(ts, ALPHA * ts), MASKF);   // valid softmax shift (>= row max)
    float negc = -c * L2E;
    float w0 = ex2f(fmaf(MASKF, L2E, negc));         // weight of masked entries

    const int* base = adj + (size_t)i * NE;          // + b*NE*NE per batch

    float Zb[8], A0[8], A1[8], A2[8];
#pragma unroll
    for (int b = 0; b < 8; b++) { Zb[b] = 0.f; A0[b] = 0.f; A1[b] = 0.f; A2[b] = 0.f; }

#define PROC_K(COMP) do {                                                    \
        float t  = s1i + s2v.COMP;                                           \
        float e  = fmaxf(t, ALPHA * t);                                      \
        float wf = ex2f(fmaf(e, L2E, negc));                                 \
        float hj0 = h0v.COMP, hj1 = h1v.COMP, hj2 = h2v.COMP;                \
        _Pragma("unroll")                                                    \
        for (int b = 0; b < 8; b++) {                                        \
            float w = (av[b].COMP != 0) ? wf : w0;                           \
            Zb[b] += w;                                                      \
            A0[b] = fmaf(w, hj0, A0[b]);                                     \
            A1[b] = fmaf(w, hj1, A1[b]);                                     \
            A2[b] = fmaf(w, hj2, A2[b]);                                     \
        }                                                                    \
    } while (0)

    // 15 full iterations (no guard -> no BSSY/BSYNC in hot loop)
#pragma unroll 2
    for (int it = 0; it < 15; it++) {
        int j0 = it * 128 + lane * 4;
        int4 av[8];
#pragma unroll
        for (int b = 0; b < 8; b++)
            av[b] = __ldcs(reinterpret_cast<const int4*>(base + (size_t)b * NE * NE + j0));
        float4 s2v = *reinterpret_cast<const float4*>(&ss2[j0]);
        float4 h0v = *reinterpret_cast<const float4*>(&sh0[j0]);
        float4 h1v = *reinterpret_cast<const float4*>(&sh1[j0]);
        float4 h2v = *reinterpret_cast<const float4*>(&sh2[j0]);
        PROC_K(x);
        PROC_K(y);
        PROC_K(z);
        PROC_K(w);
    }
    // Epilogue: j0 in [1920, 2000) -> lanes 0..19
    if (lane < 20) {
        int j0 = 1920 + lane * 4;
        int4 av[8];
#pragma unroll
        for (int b = 0; b < 8; b++)
            av[b] = __ldcs(reinterpret_cast<const int4*>(base + (size_t)b * NE * NE + j0));
        float4 s2v = *reinterpret_cast<const float4*>(&ss2[j0]);
        float4 h0v = *reinterpret_cast<const float4*>(&sh0[j0]);
        float4 h1v = *reinterpret_cast<const float4*>(&sh1[j0]);
        float4 h2v = *reinterpret_cast<const float4*>(&sh2[j0]);
        PROC_K(x);
        PROC_K(y);
        PROC_K(z);
        PROC_K(w);
    }
#undef PROC_K

    // warp reductions (32 accumulators)
#pragma unroll
    for (int b = 0; b < 8; b++) {
#pragma unroll
        for (int o = 16; o; o >>= 1) {
            Zb[b] += __shfl_xor_sync(~0u, Zb[b], o);
            A0[b] += __shfl_xor_sync(~0u, A0[b], o);
            A1[b] += __shfl_xor_sync(~0u, A1[b], o);
            A2[b] += __shfl_xor_sync(~0u, A2[b], o);
        }
    }

    if (lane == 0) {
#pragma unroll
        for (int b = 0; b < 8; b++) {
            float inv = 1.0f / Zb[b];
            float p0 = A0[b] * inv;
            float p1 = A1[b] * inv;
            float p2 = A2[b] * inv;
            float x0 = (p0 > 0.f) ? p0 : expm1f(p0);
            float x1 = (p1 > 0.f) ? p1 : expm1f(p1);
            float x2 = (p2 > 0.f) ? p2 : expm1f(p2);
            float* xp = g_x + (size_t)b * (NE * 3) + (size_t)i * 3;
            xp[0] = x0; xp[1] = x1; xp[2] = x2;
        }
    }
}

// ---------------- Kernel C: out[b,k] = x[b,:] . fc1_w[k,:] + fc1_b[k] ----------------
// Grid 64: each CTA handles 4 consecutive k, stages the FULL g_x (8x6000 floats =
// 192KB) in dynamic smem so fc1_w is the only DRAM traffic (read exactly once).
#define KM (NE * 3)          // 6000
__global__ __launch_bounds__(256) void kC(const float* __restrict__ fw,
                                          const float* __restrict__ fb,
                                          float* __restrict__ out) {
    extern __shared__ float sx[];          // [8][6000]
    __shared__ float part[8][8];           // [warp][batch]

    int tid = threadIdx.x;
    int lane = tid & 31;
    int wid = tid >> 5;

    // Stage g_x (48000 floats = 12000 float4)
    {
        const float4* gp = reinterpret_cast<const float4*>(g_x);
        float4* sp = reinterpret_cast<float4*>(sx);
        for (int q = tid; q < (NB * KM) / 4; q += 256) sp[q] = gp[q];
    }
    __syncthreads();

    int kl = wid >> 1;                     // 0..3  (k within CTA)
    int half = wid & 1;                    // m-half
    int k = blockIdx.x * 4 + kl;
    const float4* wr = reinterpret_cast<const float4*>(fw + (size_t)k * KM + half * (KM / 2));
    int base_m4 = half * (KM / 8);         // float4 index offset within a batch row (375)

    float acc[8];
#pragma unroll
    for (int b = 0; b < 8; b++) acc[b] = 0.f;

    // 750 float4 per (k,half); lanes stride 32 -> 24 iterations (guarded last)
    for (int q = lane; q < KM / 8; q += 32) {
        float4 wv = __ldcs(&wr[q]);
#pragma unroll
        for (int b = 0; b < 8; b++) {
            float4 xv = reinterpret_cast<const float4*>(sx + (size_t)b * KM)[base_m4 + q];
            acc[b] = fmaf(wv.x, xv.x, acc[b]);
            acc[b] = fmaf(wv.y, xv.y, acc[b]);
            acc[b] = fmaf(wv.z, xv.z, acc[b]);
            acc[b] = fmaf(wv.w, xv.w, acc[b]);
        }
    }

#pragma unroll
    for (int b = 0; b < 8; b++)
#pragma unroll
        for (int o = 16; o; o >>= 1)
            acc[b] += __shfl_xor_sync(~0u, acc[b], o);

    if (lane == 0) {
#pragma unroll
        for (int b = 0; b < 8; b++) part[wid][b] = acc[b];
    }
    __syncthreads();

    // 32 outputs per CTA: tid = kl*8 + b
    if (tid < 32) {
        int okl = tid >> 3;
        int b = tid & 7;
        int ok = blockIdx.x * 4 + okl;
        float s = part[2 * okl][b] + part[2 * okl + 1][b] + fb[ok];
        out[(size_t)b * NHID + ok] = s;
    }
}

extern "C" void kernel_launch(void* const* d_in, const int* in_sizes, int n_in,
                              void* d_out, int out_size) {
    const float* emb   = (const float*)d_in[0];
    const float* W     = (const float*)d_in[1];
    const float* a     = (const float*)d_in[2];
    const float* fc1_w = (const float*)d_in[3];
    const float* fc1_b = (const float*)d_in[4];
    const int*   adj   = (const int*)d_in[5];
    float* out = (float*)d_out;

    static int smem_set = 0;
    (void)smem_set;
    cudaFuncSetAttribute(kC, cudaFuncAttributeMaxDynamicSharedMemorySize,
                         NB * KM * (int)sizeof(float));

    kA<<<250, 256>>>(emb, W, a);
    kB<<<250, 256>>>(adj);
    kC<<<NHID / 4, 256, NB * KM * sizeof(float)>>>(fc1_w, fc1_b, out);
}